// round 2
// baseline (speedup 1.0000x reference)
#include <cuda_runtime.h>
#include <math.h>

#define N_NODES 50000
#define N_EDGES 500000
#define N_ET    (N_NODES + N_EDGES)   // 550000 edges incl. self-loops

// ---------------- static scratch (no allocations allowed) ----------------
__device__ float g_xl1[N_NODES * 128];
__device__ float g_xr1[N_NODES * 128];
__device__ float g_h  [N_NODES * 128];
__device__ float g_xl2[N_NODES * 64];
__device__ float g_xr2[N_NODES * 64];
__device__ int   g_cnt   [N_NODES];
__device__ int   g_start [N_NODES + 1];
__device__ int   g_cursor[N_NODES];
__device__ int   g_sorted[N_ET];

// ---------------- counting sort of edges by destination ----------------
__global__ void zero_cnt_k() {
    for (int i = blockIdx.x * blockDim.x + threadIdx.x; i < N_NODES;
         i += gridDim.x * blockDim.x)
        g_cnt[i] = 0;
}

__device__ __forceinline__ int edge_dst(const int* __restrict__ ei, int e) {
    return (e < N_EDGES) ? ei[N_EDGES + e] : (e - N_EDGES);
}
__device__ __forceinline__ int edge_src(const int* __restrict__ ei, int e) {
    return (e < N_EDGES) ? ei[e] : (e - N_EDGES);
}

__global__ void hist_k(const int* __restrict__ ei) {
    int e = blockIdx.x * blockDim.x + threadIdx.x;
    if (e < N_ET) atomicAdd(&g_cnt[edge_dst(ei, e)], 1);
}

// single-block exclusive scan of g_cnt -> g_start / g_cursor
__global__ void scan_k() {
    __shared__ int sh[1024];
    const int t = threadIdx.x;
    const int CH = (N_NODES + 1023) / 1024;  // 49
    int base = t * CH;
    int s = 0;
    for (int i = 0; i < CH; i++) {
        int idx = base + i;
        if (idx < N_NODES) s += g_cnt[idx];
    }
    sh[t] = s;
    __syncthreads();
    for (int d = 1; d < 1024; d <<= 1) {
        int v = (t >= d) ? sh[t - d] : 0;
        __syncthreads();
        sh[t] += v;
        __syncthreads();
    }
    int run = (t == 0) ? 0 : sh[t - 1];
    for (int i = 0; i < CH; i++) {
        int idx = base + i;
        if (idx < N_NODES) {
            g_start[idx]  = run;
            g_cursor[idx] = run;
            run += g_cnt[idx];
        }
    }
    if (t == 0) g_start[N_NODES] = N_ET;
}

__global__ void scatter_k(const int* __restrict__ ei) {
    int e = blockIdx.x * blockDim.x + threadIdx.x;
    if (e < N_ET) {
        int d = edge_dst(ei, e);
        int s = edge_src(ei, e);
        int pos = atomicAdd(&g_cursor[d], 1);
        g_sorted[pos] = s;
    }
}

// ---------------- fused dual GEMM:  xl = x@Wl, xr = x@Wr  (K = 128) ------
// block: NCOL threads (one output column each), ROWS=16 rows per block.
template <int NCOL>
__global__ void gemm2w_k(const float* __restrict__ x,
                         const float* __restrict__ Wl,
                         const float* __restrict__ Wr,
                         float* __restrict__ xl, float* __restrict__ xr) {
    constexpr int ROWS = 16;
    __shared__ float xs[ROWS][128];
    const int c = threadIdx.x;
    const int row0 = blockIdx.x * ROWS;

    // cooperative tile load (float4, coalesced)
    const float4* xt = (const float4*)(x + (size_t)row0 * 128);
    float4* xs4 = (float4*)&xs[0][0];
    #pragma unroll
    for (int i = c; i < ROWS * 32; i += NCOL) xs4[i] = xt[i];
    __syncthreads();

    float accl[ROWS], accr[ROWS];
    #pragma unroll
    for (int r = 0; r < ROWS; r++) { accl[r] = 0.f; accr[r] = 0.f; }

    #pragma unroll 4
    for (int k = 0; k < 128; k += 4) {
        float wl0 = Wl[(k + 0) * NCOL + c];
        float wl1 = Wl[(k + 1) * NCOL + c];
        float wl2 = Wl[(k + 2) * NCOL + c];
        float wl3 = Wl[(k + 3) * NCOL + c];
        float wr0 = Wr[(k + 0) * NCOL + c];
        float wr1 = Wr[(k + 1) * NCOL + c];
        float wr2 = Wr[(k + 2) * NCOL + c];
        float wr3 = Wr[(k + 3) * NCOL + c];
        #pragma unroll
        for (int r = 0; r < ROWS; r++) {
            float4 xv = *(const float4*)&xs[r][k];
            accl[r] = fmaf(xv.x, wl0, fmaf(xv.y, wl1,
                      fmaf(xv.z, wl2, fmaf(xv.w, wl3, accl[r]))));
            accr[r] = fmaf(xv.x, wr0, fmaf(xv.y, wr1,
                      fmaf(xv.z, wr2, fmaf(xv.w, wr3, accr[r]))));
        }
    }
    #pragma unroll
    for (int r = 0; r < ROWS; r++) {
        xl[(size_t)(row0 + r) * NCOL + c] = accl[r];
        xr[(size_t)(row0 + r) * NCOL + c] = accr[r];
    }
}

// ---------------- fused GATv2 softmax + aggregation (one warp per node) --
// H heads of C channels; HC = H*C elements per node row. VEC = HC/32 per lane.
// pass 1: per-head max of scores; pass 2: exp, denom, weighted sum.
// epilogue: /denom, +bias, optional ELU. No atomics.
template <int H, int C, bool ELU>
__global__ void agg_k(const float* __restrict__ xl, const float* __restrict__ xr,
                      const float* __restrict__ att, const float* __restrict__ bias,
                      float* __restrict__ out) {
    constexpr int HC  = H * C;
    constexpr int VEC = HC / 32;       // 4 (layer1) or 2 (layer2)
    constexpr int LPH = C / VEC;       // lanes per head: 8 or 32
    const int lane = threadIdx.x & 31;
    const int d = blockIdx.x * (blockDim.x >> 5) + (threadIdx.x >> 5);
    if (d >= N_NODES) return;
    const int base = lane * VEC;

    float xrv[VEC], attv[VEC];
    #pragma unroll
    for (int v = 0; v < VEC; v++) {
        xrv[v]  = xr[(size_t)d * HC + base + v];
        attv[v] = att[base + v];
    }
    const int s0 = g_start[d], s1 = g_start[d + 1];

    // ---- pass 1: per-head score max ----
    float mx = -INFINITY;
    for (int j = s0; j < s1; j++) {
        int src = g_sorted[j];
        const float* xp = xl + (size_t)src * HC + base;
        float xv[VEC];
        if (VEC == 4) {
            float4 t = *(const float4*)xp;
            xv[0] = t.x; xv[1] = t.y; xv[2] = t.z; xv[3] = t.w;
        } else {
            float2 t = *(const float2*)xp;
            xv[0] = t.x; xv[1] = t.y;
        }
        float s = 0.f;
        #pragma unroll
        for (int v = 0; v < VEC; v++) {
            float m = xv[v] + xrv[v];
            m = (m > 0.f) ? m : 0.2f * m;      // leaky_relu
            s = fmaf(m, attv[v], s);
        }
        #pragma unroll
        for (int w = LPH >> 1; w > 0; w >>= 1)
            s += __shfl_xor_sync(0xffffffffu, s, w);
        mx = fmaxf(mx, s);
    }

    // ---- pass 2: exp / denom / weighted sum ----
    float acc[VEC];
    #pragma unroll
    for (int v = 0; v < VEC; v++) acc[v] = 0.f;
    float den = 0.f;
    for (int j = s0; j < s1; j++) {
        int src = g_sorted[j];
        const float* xp = xl + (size_t)src * HC + base;
        float xv[VEC];
        if (VEC == 4) {
            float4 t = *(const float4*)xp;
            xv[0] = t.x; xv[1] = t.y; xv[2] = t.z; xv[3] = t.w;
        } else {
            float2 t = *(const float2*)xp;
            xv[0] = t.x; xv[1] = t.y;
        }
        float s = 0.f;
        #pragma unroll
        for (int v = 0; v < VEC; v++) {
            float m = xv[v] + xrv[v];
            m = (m > 0.f) ? m : 0.2f * m;
            s = fmaf(m, attv[v], s);
        }
        #pragma unroll
        for (int w = LPH >> 1; w > 0; w >>= 1)
            s += __shfl_xor_sync(0xffffffffu, s, w);
        float p = __expf(s - mx);
        den += p;
        #pragma unroll
        for (int v = 0; v < VEC; v++) acc[v] = fmaf(p, xv[v], acc[v]);
    }

    const float inv = 1.0f / (den + 1e-16f);
    #pragma unroll
    for (int v = 0; v < VEC; v++) {
        float r = acc[v] * inv + bias[base + v];
        if (ELU) r = (r > 0.f) ? r : expm1f(r);
        out[(size_t)d * HC + base + v] = r;
    }
}

// ---------------- launch ----------------
extern "C" void kernel_launch(void* const* d_in, const int* in_sizes, int n_in,
                              void* d_out, int out_size) {
    const float* x    = (const float*)d_in[0];
    const int*   ei   = (const int*)  d_in[1];
    const float* W1l  = (const float*)d_in[2];
    const float* W1r  = (const float*)d_in[3];
    const float* att1 = (const float*)d_in[4];
    const float* b1   = (const float*)d_in[5];
    const float* W2l  = (const float*)d_in[6];
    const float* W2r  = (const float*)d_in[7];
    const float* att2 = (const float*)d_in[8];
    const float* b2   = (const float*)d_in[9];
    float* out = (float*)d_out;

    float *xl1, *xr1, *h, *xl2, *xr2;
    cudaGetSymbolAddress((void**)&xl1, g_xl1);
    cudaGetSymbolAddress((void**)&xr1, g_xr1);
    cudaGetSymbolAddress((void**)&h,   g_h);
    cudaGetSymbolAddress((void**)&xl2, g_xl2);
    cudaGetSymbolAddress((void**)&xr2, g_xr2);

    const int ETB = (N_ET + 255) / 256;

    // edge CSR (sorted by dst)
    zero_cnt_k<<<148, 256>>>();
    hist_k<<<ETB, 256>>>(ei);
    scan_k<<<1, 1024>>>();
    scatter_k<<<ETB, 256>>>(ei);

    // layer 1
    gemm2w_k<128><<<N_NODES / 16, 128>>>(x, W1l, W1r, xl1, xr1);
    agg_k<4, 32, true><<<(N_NODES + 7) / 8, 256>>>(xl1, xr1, att1, b1, h);

    // layer 2
    gemm2w_k<64><<<N_NODES / 16, 64>>>(h, W2l, W2r, xl2, xr2);
    agg_k<1, 64, false><<<(N_NODES + 7) / 8, 256>>>(xl2, xr2, att2, b2, out);
}

// round 3
// speedup vs baseline: 1.0798x; 1.0798x over previous
#include <cuda_runtime.h>
#include <math.h>

#define N_NODES 50000
#define N_EDGES 500000
#define N_ET    (N_NODES + N_EDGES)   // 550000 edges incl. self-loops

// ---------------- static scratch (no allocations allowed) ----------------
__device__ float g_xl1[N_NODES * 128];
__device__ float g_xr1[N_NODES * 128];
__device__ float g_h  [N_NODES * 128];
__device__ float g_xl2[N_NODES * 64];
__device__ float g_xr2[N_NODES * 64];
__device__ int   g_cnt   [N_NODES];
__device__ int   g_start [N_NODES + 1];
__device__ int   g_cursor[N_NODES];
__device__ int   g_sorted[N_ET];

// ---------------- counting sort of edges by destination ----------------
__global__ void zero_cnt_k() {
    for (int i = blockIdx.x * blockDim.x + threadIdx.x; i < N_NODES;
         i += gridDim.x * blockDim.x)
        g_cnt[i] = 0;
}

__device__ __forceinline__ int edge_dst(const int* __restrict__ ei, int e) {
    return (e < N_EDGES) ? ei[N_EDGES + e] : (e - N_EDGES);
}
__device__ __forceinline__ int edge_src(const int* __restrict__ ei, int e) {
    return (e < N_EDGES) ? ei[e] : (e - N_EDGES);
}

__global__ void hist_k(const int* __restrict__ ei) {
    int e = blockIdx.x * blockDim.x + threadIdx.x;
    if (e < N_ET) atomicAdd(&g_cnt[edge_dst(ei, e)], 1);
}

// single-block exclusive scan of g_cnt -> g_start / g_cursor
__global__ void scan_k() {
    __shared__ int sh[1024];
    const int t = threadIdx.x;
    const int CH = (N_NODES + 1023) / 1024;  // 49
    int base = t * CH;
    int s = 0;
    for (int i = 0; i < CH; i++) {
        int idx = base + i;
        if (idx < N_NODES) s += g_cnt[idx];
    }
    sh[t] = s;
    __syncthreads();
    for (int d = 1; d < 1024; d <<= 1) {
        int v = (t >= d) ? sh[t - d] : 0;
        __syncthreads();
        sh[t] += v;
        __syncthreads();
    }
    int run = (t == 0) ? 0 : sh[t - 1];
    for (int i = 0; i < CH; i++) {
        int idx = base + i;
        if (idx < N_NODES) {
            g_start[idx]  = run;
            g_cursor[idx] = run;
            run += g_cnt[idx];
        }
    }
    if (t == 0) g_start[N_NODES] = N_ET;
}

__global__ void scatter_k(const int* __restrict__ ei) {
    int e = blockIdx.x * blockDim.x + threadIdx.x;
    if (e < N_ET) {
        int d = edge_dst(ei, e);
        int s = edge_src(ei, e);
        int pos = atomicAdd(&g_cursor[d], 1);
        g_sorted[pos] = s;
    }
}

// ---------------- fused dual GEMM:  xl = x@Wl, xr = x@Wr  (K = 128) ------
// Each thread owns TWO output columns (c, c+NCOL/2) of both W matrices,
// reusing each broadcast xs float4 across 16 FMAs.
template <int NCOL>
__global__ void gemm2w_k(const float* __restrict__ x,
                         const float* __restrict__ Wl,
                         const float* __restrict__ Wr,
                         float* __restrict__ xl, float* __restrict__ xr) {
    constexpr int ROWS  = 16;
    constexpr int TCOLS = NCOL / 2;
    __shared__ float xs[ROWS][128];
    const int c = threadIdx.x;            // 0 .. TCOLS-1
    const int row0 = blockIdx.x * ROWS;

    // cooperative tile load (float4, coalesced)
    const float4* xt = (const float4*)(x + (size_t)row0 * 128);
    float4* xs4 = (float4*)&xs[0][0];
    #pragma unroll
    for (int i = c; i < ROWS * 32; i += TCOLS) xs4[i] = xt[i];
    __syncthreads();

    float al0[ROWS], al1[ROWS], ar0[ROWS], ar1[ROWS];
    #pragma unroll
    for (int r = 0; r < ROWS; r++) { al0[r] = al1[r] = ar0[r] = ar1[r] = 0.f; }

    #pragma unroll 4
    for (int k = 0; k < 128; k += 4) {
        float wl0a = Wl[(k + 0) * NCOL + c];
        float wl1a = Wl[(k + 1) * NCOL + c];
        float wl2a = Wl[(k + 2) * NCOL + c];
        float wl3a = Wl[(k + 3) * NCOL + c];
        float wl0b = Wl[(k + 0) * NCOL + c + TCOLS];
        float wl1b = Wl[(k + 1) * NCOL + c + TCOLS];
        float wl2b = Wl[(k + 2) * NCOL + c + TCOLS];
        float wl3b = Wl[(k + 3) * NCOL + c + TCOLS];
        float wr0a = Wr[(k + 0) * NCOL + c];
        float wr1a = Wr[(k + 1) * NCOL + c];
        float wr2a = Wr[(k + 2) * NCOL + c];
        float wr3a = Wr[(k + 3) * NCOL + c];
        float wr0b = Wr[(k + 0) * NCOL + c + TCOLS];
        float wr1b = Wr[(k + 1) * NCOL + c + TCOLS];
        float wr2b = Wr[(k + 2) * NCOL + c + TCOLS];
        float wr3b = Wr[(k + 3) * NCOL + c + TCOLS];
        #pragma unroll
        for (int r = 0; r < ROWS; r++) {
            float4 xv = *(const float4*)&xs[r][k];
            al0[r] = fmaf(xv.x, wl0a, fmaf(xv.y, wl1a,
                     fmaf(xv.z, wl2a, fmaf(xv.w, wl3a, al0[r]))));
            al1[r] = fmaf(xv.x, wl0b, fmaf(xv.y, wl1b,
                     fmaf(xv.z, wl2b, fmaf(xv.w, wl3b, al1[r]))));
            ar0[r] = fmaf(xv.x, wr0a, fmaf(xv.y, wr1a,
                     fmaf(xv.z, wr2a, fmaf(xv.w, wr3a, ar0[r]))));
            ar1[r] = fmaf(xv.x, wr0b, fmaf(xv.y, wr1b,
                     fmaf(xv.z, wr2b, fmaf(xv.w, wr3b, ar1[r]))));
        }
    }
    #pragma unroll
    for (int r = 0; r < ROWS; r++) {
        size_t ro = (size_t)(row0 + r) * NCOL;
        xl[ro + c]         = al0[r];
        xl[ro + c + TCOLS] = al1[r];
        xr[ro + c]         = ar0[r];
        xr[ro + c + TCOLS] = ar1[r];
    }
}

// ---------------- fused GATv2 softmax + aggregation (one warp per node) --
// SINGLE PASS: no max subtraction (scores are O(5), exp is safe in fp32 and
// alpha = exp(s)/sum exp(s) is identical to the max-shifted form).
// 2-deep software pipeline on the xl[src] gather for MLP=2.
template <int H, int C, bool ELU>
__global__ void agg_k(const float* __restrict__ xl, const float* __restrict__ xr,
                      const float* __restrict__ att, const float* __restrict__ bias,
                      float* __restrict__ out) {
    constexpr int HC  = H * C;
    constexpr int VEC = HC / 32;       // 4 (layer1) or 2 (layer2)
    constexpr int LPH = C / VEC;       // lanes per head: 8 or 32
    const int lane = threadIdx.x & 31;
    const int d = blockIdx.x * (blockDim.x >> 5) + (threadIdx.x >> 5);
    if (d >= N_NODES) return;
    const int base = lane * VEC;

    float xrv[VEC], attv[VEC];
    #pragma unroll
    for (int v = 0; v < VEC; v++) {
        xrv[v]  = xr[(size_t)d * HC + base + v];
        attv[v] = att[base + v];
    }
    const int s0 = g_start[d], s1 = g_start[d + 1];

    float acc[VEC];
    #pragma unroll
    for (int v = 0; v < VEC; v++) acc[v] = 0.f;
    float den = 0.f;

    // prefetch first edge
    float xn[VEC];
    if (s0 < s1) {
        const float* xp = xl + (size_t)g_sorted[s0] * HC + base;
        if (VEC == 4) {
            float4 t = *(const float4*)xp;
            xn[0] = t.x; xn[1] = t.y; xn[2] = t.z; xn[3] = t.w;
        } else {
            float2 t = *(const float2*)xp;
            xn[0] = t.x; xn[1] = t.y;
        }
    }

    for (int j = s0; j < s1; j++) {
        float xv[VEC];
        #pragma unroll
        for (int v = 0; v < VEC; v++) xv[v] = xn[v];

        if (j + 1 < s1) {   // prefetch next edge while computing current
            const float* xp = xl + (size_t)g_sorted[j + 1] * HC + base;
            if (VEC == 4) {
                float4 t = *(const float4*)xp;
                xn[0] = t.x; xn[1] = t.y; xn[2] = t.z; xn[3] = t.w;
            } else {
                float2 t = *(const float2*)xp;
                xn[0] = t.x; xn[1] = t.y;
            }
        }

        float s = 0.f;
        #pragma unroll
        for (int v = 0; v < VEC; v++) {
            float m = xv[v] + xrv[v];
            m = (m > 0.f) ? m : 0.2f * m;      // leaky_relu
            s = fmaf(m, attv[v], s);
        }
        #pragma unroll
        for (int w = LPH >> 1; w > 0; w >>= 1)
            s += __shfl_xor_sync(0xffffffffu, s, w);

        float p = __expf(s);
        den += p;
        #pragma unroll
        for (int v = 0; v < VEC; v++) acc[v] = fmaf(p, xv[v], acc[v]);
    }

    const float inv = 1.0f / (den + 1e-16f);
    #pragma unroll
    for (int v = 0; v < VEC; v++) {
        float r = acc[v] * inv + bias[base + v];
        if (ELU) r = (r > 0.f) ? r : expm1f(r);
        out[(size_t)d * HC + base + v] = r;
    }
}

// ---------------- launch ----------------
extern "C" void kernel_launch(void* const* d_in, const int* in_sizes, int n_in,
                              void* d_out, int out_size) {
    const float* x    = (const float*)d_in[0];
    const int*   ei   = (const int*)  d_in[1];
    const float* W1l  = (const float*)d_in[2];
    const float* W1r  = (const float*)d_in[3];
    const float* att1 = (const float*)d_in[4];
    const float* b1   = (const float*)d_in[5];
    const float* W2l  = (const float*)d_in[6];
    const float* W2r  = (const float*)d_in[7];
    const float* att2 = (const float*)d_in[8];
    const float* b2   = (const float*)d_in[9];
    float* out = (float*)d_out;

    float *xl1, *xr1, *h, *xl2, *xr2;
    cudaGetSymbolAddress((void**)&xl1, g_xl1);
    cudaGetSymbolAddress((void**)&xr1, g_xr1);
    cudaGetSymbolAddress((void**)&h,   g_h);
    cudaGetSymbolAddress((void**)&xl2, g_xl2);
    cudaGetSymbolAddress((void**)&xr2, g_xr2);

    const int ETB = (N_ET + 255) / 256;

    // edge CSR (sorted by dst)
    zero_cnt_k<<<148, 256>>>();
    hist_k<<<ETB, 256>>>(ei);
    scan_k<<<1, 1024>>>();
    scatter_k<<<ETB, 256>>>(ei);

    // layer 1
    gemm2w_k<128><<<N_NODES / 16, 64>>>(x, W1l, W1r, xl1, xr1);
    agg_k<4, 32, true><<<(N_NODES + 7) / 8, 256>>>(xl1, xr1, att1, b1, h);

    // layer 2
    gemm2w_k<64><<<N_NODES / 16, 32>>>(h, W2l, W2r, xl2, xr2);
    agg_k<1, 64, false><<<(N_NODES + 7) / 8, 256>>>(xl2, xr2, att2, b2, out);
}

// round 4
// speedup vs baseline: 1.1302x; 1.0467x over previous
#include <cuda_runtime.h>
#include <math.h>

#define N_NODES 50000
#define N_EDGES 500000
#define N_ET    (N_NODES + N_EDGES)   // 550000 edges incl. self-loops

// ---------------- static scratch (no allocations allowed) ----------------
__device__ float g_xl1[N_NODES * 128];
__device__ float g_xr1[N_NODES * 128];
__device__ float g_h  [N_NODES * 128];
__device__ float g_xl2[N_NODES * 64];
__device__ float g_xr2[N_NODES * 64];
__device__ int   g_cnt   [N_NODES];
__device__ int   g_start [N_NODES + 1];
__device__ int   g_cursor[N_NODES];
__device__ int   g_sorted[N_ET];

// ---------------- counting sort of edges by destination ----------------
__global__ void zero_cnt_k() {
    for (int i = blockIdx.x * blockDim.x + threadIdx.x; i < N_NODES;
         i += gridDim.x * blockDim.x)
        g_cnt[i] = 0;
}

__device__ __forceinline__ int edge_dst(const int* __restrict__ ei, int e) {
    return (e < N_EDGES) ? ei[N_EDGES + e] : (e - N_EDGES);
}
__device__ __forceinline__ int edge_src(const int* __restrict__ ei, int e) {
    return (e < N_EDGES) ? ei[e] : (e - N_EDGES);
}

__global__ void hist_k(const int* __restrict__ ei) {
    int e = blockIdx.x * blockDim.x + threadIdx.x;
    if (e < N_ET) atomicAdd(&g_cnt[edge_dst(ei, e)], 1);
}

// single-block exclusive scan of g_cnt -> g_start / g_cursor
__global__ void scan_k() {
    __shared__ int sh[1024];
    const int t = threadIdx.x;
    const int CH = (N_NODES + 1023) / 1024;  // 49
    int base = t * CH;
    int s = 0;
    for (int i = 0; i < CH; i++) {
        int idx = base + i;
        if (idx < N_NODES) s += g_cnt[idx];
    }
    sh[t] = s;
    __syncthreads();
    for (int d = 1; d < 1024; d <<= 1) {
        int v = (t >= d) ? sh[t - d] : 0;
        __syncthreads();
        sh[t] += v;
        __syncthreads();
    }
    int run = (t == 0) ? 0 : sh[t - 1];
    for (int i = 0; i < CH; i++) {
        int idx = base + i;
        if (idx < N_NODES) {
            g_start[idx]  = run;
            g_cursor[idx] = run;
            run += g_cnt[idx];
        }
    }
    if (t == 0) g_start[N_NODES] = N_ET;
}

__global__ void scatter_k(const int* __restrict__ ei) {
    int e = blockIdx.x * blockDim.x + threadIdx.x;
    if (e < N_ET) {
        int d = edge_dst(ei, e);
        int s = edge_src(ei, e);
        int pos = atomicAdd(&g_cursor[d], 1);
        g_sorted[pos] = s;
    }
}

// ---------------- packed-f32x2 helpers ----------------
typedef unsigned long long ull;

__device__ __forceinline__ ull dup2(float w) {
    ull r;
    asm("mov.b64 %0, {%1, %1};" : "=l"(r) : "r"(__float_as_uint(w)));
    return r;
}
__device__ __forceinline__ void ffma2(ull& d, ull a, ull b) {
    asm("fma.rn.f32x2 %0, %1, %2, %0;" : "+l"(d) : "l"(a), "l"(b));
}
__device__ __forceinline__ void unpack2(ull v, float& lo, float& hi) {
    unsigned int l, h;
    asm("mov.b64 {%0, %1}, %2;" : "=r"(l), "=r"(h) : "l"(v));
    lo = __uint_as_float(l);
    hi = __uint_as_float(h);
}

// ---------------- fused dual GEMM via FFMA2:  xl = x@Wl, xr = x@Wr --------
// K = 128. Each thread owns TWO columns (c, c+NCOL/2) of BOTH W matrices.
// x tile staged TRANSPOSED in shared so a row-PAIR is one 8-byte broadcast
// LDS usable directly as an f32x2 operand; W scalars duplicated once per k.
// fma.rn.f32x2 = 2 fp32 FMAs per issue slot -> 2x the FFMA floor.
template <int NCOL>
__global__ void gemm2w_k(const float* __restrict__ x,
                         const float* __restrict__ Wl,
                         const float* __restrict__ Wr,
                         float* __restrict__ xl, float* __restrict__ xr) {
    constexpr int ROWS = 16;
    constexpr int RP   = ROWS / 2;          // 8 row pairs
    constexpr int T    = NCOL / 2;          // threads per block
    constexpr int STR  = 18;                // shared row stride (floats, even)
    __shared__ float xs_t[128][STR];        // transposed tile

    const int c    = threadIdx.x;           // 0 .. T-1
    const int row0 = blockIdx.x * ROWS;

    // cooperative transposed load: i -> (k4 = i&31, r = i>>5), coalesced LDG
    const float4* xt = (const float4*)(x + (size_t)row0 * 128);
    for (int i = c; i < ROWS * 32; i += T) {
        int k4 = i & 31;
        int r  = i >> 5;
        float4 v = xt[r * 32 + k4];
        xs_t[4 * k4 + 0][r] = v.x;
        xs_t[4 * k4 + 1][r] = v.y;
        xs_t[4 * k4 + 2][r] = v.z;
        xs_t[4 * k4 + 3][r] = v.w;
    }
    __syncthreads();

    ull la[RP], lb[RP], ra[RP], rb[RP];
    #pragma unroll
    for (int p = 0; p < RP; p++) { la[p] = lb[p] = ra[p] = rb[p] = 0ULL; }

    #pragma unroll 4
    for (int k = 0; k < 128; k++) {
        ull wla = dup2(Wl[k * NCOL + c]);
        ull wlb = dup2(Wl[k * NCOL + c + T]);
        ull wra = dup2(Wr[k * NCOL + c]);
        ull wrb = dup2(Wr[k * NCOL + c + T]);
        const ull* xp = (const ull*)&xs_t[k][0];
        #pragma unroll
        for (int p = 0; p < RP; p++) {
            ull xv = xp[p];                 // broadcast row-pair
            ffma2(la[p], xv, wla);
            ffma2(lb[p], xv, wlb);
            ffma2(ra[p], xv, wra);
            ffma2(rb[p], xv, wrb);
        }
    }

    #pragma unroll
    for (int p = 0; p < RP; p++) {
        float v0, v1;
        size_t r0 = (size_t)(row0 + 2 * p) * NCOL;
        size_t r1 = (size_t)(row0 + 2 * p + 1) * NCOL;
        unpack2(la[p], v0, v1); xl[r0 + c]     = v0; xl[r1 + c]     = v1;
        unpack2(lb[p], v0, v1); xl[r0 + c + T] = v0; xl[r1 + c + T] = v1;
        unpack2(ra[p], v0, v1); xr[r0 + c]     = v0; xr[r1 + c]     = v1;
        unpack2(rb[p], v0, v1); xr[r0 + c + T] = v0; xr[r1 + c + T] = v1;
    }
}

// ---------------- fused GATv2 softmax + aggregation (one warp per node) --
// SINGLE PASS: no max subtraction (scores are O(5), fp32 exp safe; alpha
// identical to the max-shifted form). 2-deep pipeline on the xl[src] gather.
template <int H, int C, bool ELU>
__global__ void agg_k(const float* __restrict__ xl, const float* __restrict__ xr,
                      const float* __restrict__ att, const float* __restrict__ bias,
                      float* __restrict__ out) {
    constexpr int HC  = H * C;
    constexpr int VEC = HC / 32;       // 4 (layer1) or 2 (layer2)
    constexpr int LPH = C / VEC;       // lanes per head: 8 or 32
    const int lane = threadIdx.x & 31;
    const int d = blockIdx.x * (blockDim.x >> 5) + (threadIdx.x >> 5);
    if (d >= N_NODES) return;
    const int base = lane * VEC;

    float xrv[VEC], attv[VEC];
    #pragma unroll
    for (int v = 0; v < VEC; v++) {
        xrv[v]  = xr[(size_t)d * HC + base + v];
        attv[v] = att[base + v];
    }
    const int s0 = g_start[d], s1 = g_start[d + 1];

    float acc[VEC];
    #pragma unroll
    for (int v = 0; v < VEC; v++) acc[v] = 0.f;
    float den = 0.f;

    float xn[VEC];
    if (s0 < s1) {
        const float* xp = xl + (size_t)g_sorted[s0] * HC + base;
        if (VEC == 4) {
            float4 t = *(const float4*)xp;
            xn[0] = t.x; xn[1] = t.y; xn[2] = t.z; xn[3] = t.w;
        } else {
            float2 t = *(const float2*)xp;
            xn[0] = t.x; xn[1] = t.y;
        }
    }

    for (int j = s0; j < s1; j++) {
        float xv[VEC];
        #pragma unroll
        for (int v = 0; v < VEC; v++) xv[v] = xn[v];

        if (j + 1 < s1) {
            const float* xp = xl + (size_t)g_sorted[j + 1] * HC + base;
            if (VEC == 4) {
                float4 t = *(const float4*)xp;
                xn[0] = t.x; xn[1] = t.y; xn[2] = t.z; xn[3] = t.w;
            } else {
                float2 t = *(const float2*)xp;
                xn[0] = t.x; xn[1] = t.y;
            }
        }

        float s = 0.f;
        #pragma unroll
        for (int v = 0; v < VEC; v++) {
            float m = xv[v] + xrv[v];
            m = (m > 0.f) ? m : 0.2f * m;      // leaky_relu
            s = fmaf(m, attv[v], s);
        }
        #pragma unroll
        for (int w = LPH >> 1; w > 0; w >>= 1)
            s += __shfl_xor_sync(0xffffffffu, s, w);

        float p = __expf(s);
        den += p;
        #pragma unroll
        for (int v = 0; v < VEC; v++) acc[v] = fmaf(p, xv[v], acc[v]);
    }

    const float inv = 1.0f / (den + 1e-16f);
    #pragma unroll
    for (int v = 0; v < VEC; v++) {
        float r = acc[v] * inv + bias[base + v];
        if (ELU) r = (r > 0.f) ? r : expm1f(r);
        out[(size_t)d * HC + base + v] = r;
    }
}

// ---------------- launch ----------------
extern "C" void kernel_launch(void* const* d_in, const int* in_sizes, int n_in,
                              void* d_out, int out_size) {
    const float* x    = (const float*)d_in[0];
    const int*   ei   = (const int*)  d_in[1];
    const float* W1l  = (const float*)d_in[2];
    const float* W1r  = (const float*)d_in[3];
    const float* att1 = (const float*)d_in[4];
    const float* b1   = (const float*)d_in[5];
    const float* W2l  = (const float*)d_in[6];
    const float* W2r  = (const float*)d_in[7];
    const float* att2 = (const float*)d_in[8];
    const float* b2   = (const float*)d_in[9];
    float* out = (float*)d_out;

    float *xl1, *xr1, *h, *xl2, *xr2;
    cudaGetSymbolAddress((void**)&xl1, g_xl1);
    cudaGetSymbolAddress((void**)&xr1, g_xr1);
    cudaGetSymbolAddress((void**)&h,   g_h);
    cudaGetSymbolAddress((void**)&xl2, g_xl2);
    cudaGetSymbolAddress((void**)&xr2, g_xr2);

    const int ETB = (N_ET + 255) / 256;

    // edge CSR (sorted by dst)
    zero_cnt_k<<<148, 256>>>();
    hist_k<<<ETB, 256>>>(ei);
    scan_k<<<1, 1024>>>();
    scatter_k<<<ETB, 256>>>(ei);

    // layer 1
    gemm2w_k<128><<<N_NODES / 16, 64>>>(x, W1l, W1r, xl1, xr1);
    agg_k<4, 32, true><<<(N_NODES + 7) / 8, 256>>>(xl1, xr1, att1, b1, h);

    // layer 2
    gemm2w_k<64><<<N_NODES / 16, 32>>>(h, W2l, W2r, xl2, xr2);
    agg_k<1, 64, false><<<(N_NODES + 7) / 8, 256>>>(xl2, xr2, att2, b2, out);
}

// round 6
// speedup vs baseline: 1.2295x; 1.0879x over previous
#include <cuda_runtime.h>
#include <cuda_bf16.h>
#include <math.h>
#include <stdint.h>

#define N_NODES 50000
#define N_EDGES 500000
#define N_ET    (N_NODES + N_EDGES)   // 550000 edges incl. self-loops

// ---------------- static scratch (no allocations allowed) ----------------
__device__ float g_xl1[N_NODES * 128];
__device__ float g_xr1[N_NODES * 128];
__device__ __nv_bfloat16 g_hhi[N_NODES * 128];
__device__ __nv_bfloat16 g_hlo[N_NODES * 128];
__device__ float g_xl2[N_NODES * 64];
__device__ float g_xr2[N_NODES * 64];
__device__ int   g_cnt   [N_NODES];
__device__ int   g_start [N_NODES + 1];
__device__ int   g_cursor[N_NODES];
__device__ int   g_sorted[N_ET];
// bf16 weight images, plain [n][k] row-major (ldmatrix-native for B operand)
__device__ __nv_bfloat16 g_B1hi[256 * 128];
__device__ __nv_bfloat16 g_B1lo[256 * 128];
__device__ __nv_bfloat16 g_B2hi[128 * 128];
__device__ __nv_bfloat16 g_B2lo[128 * 128];

// ---------------- counting sort of edges by destination ----------------
__global__ void zero_cnt_k() {
    for (int i = blockIdx.x * blockDim.x + threadIdx.x; i < N_NODES;
         i += gridDim.x * blockDim.x)
        g_cnt[i] = 0;
}
__device__ __forceinline__ int edge_dst(const int* __restrict__ ei, int e) {
    return (e < N_EDGES) ? ei[N_EDGES + e] : (e - N_EDGES);
}
__device__ __forceinline__ int edge_src(const int* __restrict__ ei, int e) {
    return (e < N_EDGES) ? ei[e] : (e - N_EDGES);
}
__global__ void hist_k(const int* __restrict__ ei) {
    int e = blockIdx.x * blockDim.x + threadIdx.x;
    if (e < N_ET) atomicAdd(&g_cnt[edge_dst(ei, e)], 1);
}
__global__ void scan_k() {
    __shared__ int sh[1024];
    const int t = threadIdx.x;
    const int CH = (N_NODES + 1023) / 1024;  // 49
    int base = t * CH;
    int s = 0;
    for (int i = 0; i < CH; i++) {
        int idx = base + i;
        if (idx < N_NODES) s += g_cnt[idx];
    }
    sh[t] = s;
    __syncthreads();
    for (int d = 1; d < 1024; d <<= 1) {
        int v = (t >= d) ? sh[t - d] : 0;
        __syncthreads();
        sh[t] += v;
        __syncthreads();
    }
    int run = (t == 0) ? 0 : sh[t - 1];
    for (int i = 0; i < CH; i++) {
        int idx = base + i;
        if (idx < N_NODES) {
            g_start[idx]  = run;
            g_cursor[idx] = run;
            run += g_cnt[idx];
        }
    }
    if (t == 0) g_start[N_NODES] = N_ET;
}
__global__ void scatter_k(const int* __restrict__ ei) {
    int e = blockIdx.x * blockDim.x + threadIdx.x;
    if (e < N_ET) {
        int d = edge_dst(ei, e);
        int s = edge_src(ei, e);
        int pos = atomicAdd(&g_cursor[d], 1);
        g_sorted[pos] = s;
    }
}

// ---------------- weight -> bf16 hi/lo images, [n][k] row-major ----------
__global__ void bimg_k(const float* __restrict__ W1l, const float* __restrict__ W1r,
                       const float* __restrict__ W2l, const float* __restrict__ W2r) {
    int t = blockIdx.x * blockDim.x + threadIdx.x;
    if (t < 256 * 128) {                    // layer 1
        int n = t >> 7, k = t & 127;
        float v = (n < 128) ? W1l[k * 128 + n] : W1r[k * 128 + (n - 128)];
        __nv_bfloat16 h = __float2bfloat16_rn(v);
        g_B1hi[n * 128 + k] = h;
        g_B1lo[n * 128 + k] = __float2bfloat16_rn(v - __bfloat162float(h));
    } else if (t < 256 * 128 + 128 * 128) { // layer 2
        int t2 = t - 256 * 128;
        int n = t2 >> 7, k = t2 & 127;
        float v = (n < 64) ? W2l[k * 64 + n] : W2r[k * 64 + (n - 64)];
        __nv_bfloat16 h = __float2bfloat16_rn(v);
        g_B2hi[n * 128 + k] = h;
        g_B2lo[n * 128 + k] = __float2bfloat16_rn(v - __bfloat162float(h));
    }
}

// ---------------- mma.sync helpers (sm_80 baseline, works on sm_103) -----
__device__ __forceinline__ void ldsm_x4(uint32_t* r, uint32_t addr) {
    asm volatile("ldmatrix.sync.aligned.m8n8.x4.shared.b16 {%0,%1,%2,%3}, [%4];"
        : "=r"(r[0]), "=r"(r[1]), "=r"(r[2]), "=r"(r[3]) : "r"(addr));
}
__device__ __forceinline__ void mma_bf16(float* d, const uint32_t* a,
                                         uint32_t b0, uint32_t b1) {
    asm volatile("mma.sync.aligned.m16n8k16.row.col.f32.bf16.bf16.f32 "
        "{%0,%1,%2,%3}, {%4,%5,%6,%7}, {%8,%9}, {%0,%1,%2,%3};"
        : "+f"(d[0]), "+f"(d[1]), "+f"(d[2]), "+f"(d[3])
        : "r"(a[0]), "r"(a[1]), "r"(a[2]), "r"(a[3]), "r"(b0), "r"(b1));
}

// ---------------- HMMA split-bf16 dual GEMM ----------------
// D[128, 128-chunk] = Ahi@Bhi + Ahi@Blo + Alo@Bhi, fp32 accum.
// A: 128 node rows x K=128 (hi/lo). B: 128 output-cols x K=128 (hi/lo image,
// row nh*128 offset). Output cols [0,HALF) -> xl, rest -> xr.
// SMEM rows padded to 136 bf16 (272 B) for conflict-free ldmatrix.
template <int HALF, bool CONVERT>
__global__ void __launch_bounds__(256, 1)
gemm_tc_k(const float* __restrict__ xf,
          const __nv_bfloat16* __restrict__ ahi_g,
          const __nv_bfloat16* __restrict__ alo_g,
          const __nv_bfloat16* __restrict__ bhi_img,
          const __nv_bfloat16* __restrict__ blo_img,
          float* __restrict__ xl, float* __restrict__ xr) {
    extern __shared__ char smem[];
    constexpr int STRB = 272;                 // 136 bf16 per row
    constexpr int A_HI = 0;
    constexpr int A_LO = A_HI + 128 * STRB;   // 34816
    constexpr int B_HI = A_LO + 128 * STRB;
    constexpr int B_LO = B_HI + 128 * STRB;
    const int tid = threadIdx.x, wid = tid >> 5, lane = tid & 31;
    const int row0 = blockIdx.x * 128;
    const int nh   = blockIdx.y;
    uint32_t sb;
    asm("{ .reg .u64 t; cvta.to.shared.u64 t, %1; cvt.u32.u64 %0, t; }"
        : "=r"(sb) : "l"(smem));

    // ---- B tiles: row copy with padding ----
    {
        const uint4* s1 = (const uint4*)bhi_img;
        const uint4* s2 = (const uint4*)blo_img;
        for (int i = tid; i < 128 * 16; i += 256) {
            int r = i >> 4, seg = i & 15;
            *(uint4*)(smem + B_HI + r * STRB + seg * 16) = s1[(nh * 128 + r) * 16 + seg];
            *(uint4*)(smem + B_LO + r * STRB + seg * 16) = s2[(nh * 128 + r) * 16 + seg];
        }
    }
    // ---- A tiles ----
    if (CONVERT) {
        const float4* xt = (const float4*)(xf + (size_t)row0 * 128);
        for (int idx = tid; idx < 4096; idx += 256) {
            int r = idx >> 5, k4 = idx & 31, c0 = k4 * 4;
            float4 v = make_float4(0.f, 0.f, 0.f, 0.f);
            if (row0 + r < N_NODES) v = xt[idx];
            __nv_bfloat16 h0 = __float2bfloat16_rn(v.x);
            __nv_bfloat16 h1 = __float2bfloat16_rn(v.y);
            __nv_bfloat16 h2 = __float2bfloat16_rn(v.z);
            __nv_bfloat16 h3 = __float2bfloat16_rn(v.w);
            ushort hh[4] = { __bfloat16_as_ushort(h0), __bfloat16_as_ushort(h1),
                             __bfloat16_as_ushort(h2), __bfloat16_as_ushort(h3) };
            ushort ll[4] = {
                __bfloat16_as_ushort(__float2bfloat16_rn(v.x - __bfloat162float(h0))),
                __bfloat16_as_ushort(__float2bfloat16_rn(v.y - __bfloat162float(h1))),
                __bfloat16_as_ushort(__float2bfloat16_rn(v.z - __bfloat162float(h2))),
                __bfloat16_as_ushort(__float2bfloat16_rn(v.w - __bfloat162float(h3))) };
            *(uint2*)(smem + A_HI + r * STRB + c0 * 2) = *(const uint2*)hh;
            *(uint2*)(smem + A_LO + r * STRB + c0 * 2) = *(const uint2*)ll;
        }
    } else {
        const uint4* s1 = (const uint4*)ahi_g;
        const uint4* s2 = (const uint4*)alo_g;
        for (int idx = tid; idx < 2048; idx += 256) {
            int r = idx >> 4, seg = idx & 15;
            uint4 v1 = make_uint4(0u, 0u, 0u, 0u), v2 = v1;
            if (row0 + r < N_NODES) {
                v1 = s1[(size_t)(row0 + r) * 16 + seg];
                v2 = s2[(size_t)(row0 + r) * 16 + seg];
            }
            *(uint4*)(smem + A_HI + r * STRB + seg * 16) = v1;
            *(uint4*)(smem + A_LO + r * STRB + seg * 16) = v2;
        }
    }
    __syncthreads();

    // ---- mainloop: per warp, 16 rows x 128 cols ----
    const int m0 = wid * 16;
    // A ldmatrix address: lanes 0-15 rows m0..m0+15 @k, lanes 16-31 @k+8
    uint32_t aRow = m0 + (lane & 15);
    uint32_t aCol = (lane >> 4) * 16;              // bytes
    uint32_t aAddrH = sb + A_HI + aRow * STRB + aCol;
    uint32_t aAddrL = sb + A_LO + aRow * STRB + aCol;
    // B ldmatrix address: groups of 8 lanes -> (n, n k+8, n+8, n+8 k+8)
    int g = lane >> 3;
    uint32_t bRow = (lane & 7) + ((g & 2) << 2);   // +8 for g>=2
    uint32_t bCol = (g & 1) * 16;                  // bytes
    uint32_t bAddrH = sb + B_HI + bRow * STRB + bCol;
    uint32_t bAddrL = sb + B_LO + bRow * STRB + bCol;

    float acc[16][4];
    #pragma unroll
    for (int i = 0; i < 16; i++)
        #pragma unroll
        for (int j = 0; j < 4; j++) acc[i][j] = 0.f;

    #pragma unroll 1
    for (int ks = 0; ks < 8; ks++) {
        uint32_t ka = ks * 32;                     // 16 bf16 = 32 bytes
        uint32_t ah[4], al[4];
        ldsm_x4(ah, aAddrH + ka);
        ldsm_x4(al, aAddrL + ka);
        #pragma unroll
        for (int nt2 = 0; nt2 < 8; nt2++) {
            uint32_t off = nt2 * (16 * STRB) + ka;
            uint32_t bh[4], bl[4];
            ldsm_x4(bh, bAddrH + off);
            ldsm_x4(bl, bAddrL + off);
            mma_bf16(acc[nt2 * 2],     ah, bh[0], bh[1]);
            mma_bf16(acc[nt2 * 2],     ah, bl[0], bl[1]);
            mma_bf16(acc[nt2 * 2],     al, bh[0], bh[1]);
            mma_bf16(acc[nt2 * 2 + 1], ah, bh[2], bh[3]);
            mma_bf16(acc[nt2 * 2 + 1], ah, bl[2], bl[3]);
            mma_bf16(acc[nt2 * 2 + 1], al, bh[2], bh[3]);
        }
    }

    // ---- epilogue: direct float2 stores (full 32B sectors) ----
    const int rq = lane >> 2;           // 0..7
    const int cq = (lane & 3) * 2;
    const int r0g = row0 + m0 + rq;
    const int r1g = r0g + 8;
    #pragma unroll
    for (int nt = 0; nt < 16; nt++) {
        int gc = nh * 128 + nt * 8 + cq;
        float2 v0 = make_float2(acc[nt][0], acc[nt][1]);
        float2 v1 = make_float2(acc[nt][2], acc[nt][3]);
        if (gc < HALF) {
            if (r0g < N_NODES) *(float2*)&xl[(size_t)r0g * HALF + gc] = v0;
            if (r1g < N_NODES) *(float2*)&xl[(size_t)r1g * HALF + gc] = v1;
        } else {
            int g2 = gc - HALF;
            if (r0g < N_NODES) *(float2*)&xr[(size_t)r0g * HALF + g2] = v0;
            if (r1g < N_NODES) *(float2*)&xr[(size_t)r1g * HALF + g2] = v1;
        }
    }
}

// ---------------- fused GATv2 softmax + aggregation (one warp per node) --
// Single pass, no max-subtraction (scores O(5), fp32-exp safe).
// MODE 0: fp32 out + bias. MODE 1: bias + ELU, output split bf16 hi/lo.
template <int H, int C, int MODE>
__global__ void agg_k(const float* __restrict__ xl, const float* __restrict__ xr,
                      const float* __restrict__ att, const float* __restrict__ bias,
                      float* __restrict__ outf,
                      __nv_bfloat16* __restrict__ ohi, __nv_bfloat16* __restrict__ olo) {
    constexpr int HC  = H * C;
    constexpr int VEC = HC / 32;       // 4 (layer1) or 2 (layer2)
    constexpr int LPH = C / VEC;       // lanes per head
    const int lane = threadIdx.x & 31;
    const int d = blockIdx.x * (blockDim.x >> 5) + (threadIdx.x >> 5);
    if (d >= N_NODES) return;
    const int base = lane * VEC;

    float xrv[VEC], attv[VEC];
    #pragma unroll
    for (int v = 0; v < VEC; v++) {
        xrv[v]  = xr[(size_t)d * HC + base + v];
        attv[v] = att[base + v];
    }
    const int s0 = g_start[d], s1 = g_start[d + 1];

    float acc[VEC];
    #pragma unroll
    for (int v = 0; v < VEC; v++) acc[v] = 0.f;
    float den = 0.f;

    float xn[VEC];
    if (s0 < s1) {
        const float* xp = xl + (size_t)g_sorted[s0] * HC + base;
        if (VEC == 4) {
            float4 t = *(const float4*)xp;
            xn[0] = t.x; xn[1] = t.y; xn[2] = t.z; xn[3] = t.w;
        } else {
            float2 t = *(const float2*)xp;
            xn[0] = t.x; xn[1] = t.y;
        }
    }
    for (int j = s0; j < s1; j++) {
        float xv[VEC];
        #pragma unroll
        for (int v = 0; v < VEC; v++) xv[v] = xn[v];
        if (j + 1 < s1) {
            const float* xp = xl + (size_t)g_sorted[j + 1] * HC + base;
            if (VEC == 4) {
                float4 t = *(const float4*)xp;
                xn[0] = t.x; xn[1] = t.y; xn[2] = t.z; xn[3] = t.w;
            } else {
                float2 t = *(const float2*)xp;
                xn[0] = t.x; xn[1] = t.y;
            }
        }
        float s = 0.f;
        #pragma unroll
        for (int v = 0; v < VEC; v++) {
            float m = xv[v] + xrv[v];
            m = (m > 0.f) ? m : 0.2f * m;      // leaky_relu
            s = fmaf(m, attv[v], s);
        }
        #pragma unroll
        for (int w = LPH >> 1; w > 0; w >>= 1)
            s += __shfl_xor_sync(0xffffffffu, s, w);
        float p = __expf(s);
        den += p;
        #pragma unroll
        for (int v = 0; v < VEC; v++) acc[v] = fmaf(p, xv[v], acc[v]);
    }

    const float inv = 1.0f / (den + 1e-16f);
    if (MODE == 0) {
        #pragma unroll
        for (int v = 0; v < VEC; v++)
            outf[(size_t)d * HC + base + v] = acc[v] * inv + bias[base + v];
    } else {
        ushort hh[VEC], ll[VEC];
        #pragma unroll
        for (int v = 0; v < VEC; v++) {
            float r = acc[v] * inv + bias[base + v];
            r = (r > 0.f) ? r : (__expf(r) - 1.0f);   // ELU
            __nv_bfloat16 hb = __float2bfloat16_rn(r);
            hh[v] = __bfloat16_as_ushort(hb);
            ll[v] = __bfloat16_as_ushort(__float2bfloat16_rn(r - __bfloat162float(hb)));
        }
        size_t o = ((size_t)d * HC + base) >> 2;      // VEC==4: uint2 granules
        ((uint2*)ohi)[o] = *(const uint2*)hh;
        ((uint2*)olo)[o] = *(const uint2*)ll;
    }
}

// ---------------- launch ----------------
extern "C" void kernel_launch(void* const* d_in, const int* in_sizes, int n_in,
                              void* d_out, int out_size) {
    const float* x    = (const float*)d_in[0];
    const int*   ei   = (const int*)  d_in[1];
    const float* W1l  = (const float*)d_in[2];
    const float* W1r  = (const float*)d_in[3];
    const float* att1 = (const float*)d_in[4];
    const float* b1   = (const float*)d_in[5];
    const float* W2l  = (const float*)d_in[6];
    const float* W2r  = (const float*)d_in[7];
    const float* att2 = (const float*)d_in[8];
    const float* b2   = (const float*)d_in[9];
    float* out = (float*)d_out;

    float *xl1, *xr1, *xl2, *xr2;
    __nv_bfloat16 *hhi, *hlo, *b1hi, *b1lo, *b2hi, *b2lo;
    cudaGetSymbolAddress((void**)&xl1, g_xl1);
    cudaGetSymbolAddress((void**)&xr1, g_xr1);
    cudaGetSymbolAddress((void**)&hhi, g_hhi);
    cudaGetSymbolAddress((void**)&hlo, g_hlo);
    cudaGetSymbolAddress((void**)&xl2, g_xl2);
    cudaGetSymbolAddress((void**)&xr2, g_xr2);
    cudaGetSymbolAddress((void**)&b1hi, g_B1hi);
    cudaGetSymbolAddress((void**)&b1lo, g_B1lo);
    cudaGetSymbolAddress((void**)&b2hi, g_B2hi);
    cudaGetSymbolAddress((void**)&b2lo, g_B2lo);

    constexpr int SMEMB = 4 * 128 * 272;   // 139264
    cudaFuncSetAttribute(gemm_tc_k<128, true>,
                         cudaFuncAttributeMaxDynamicSharedMemorySize, SMEMB);
    cudaFuncSetAttribute(gemm_tc_k<64, false>,
                         cudaFuncAttributeMaxDynamicSharedMemorySize, SMEMB);

    const int ETB = (N_ET + 255) / 256;
    const int GT  = (N_NODES + 127) / 128;   // 391 gemm tiles

    // edge CSR (sorted by dst)
    zero_cnt_k<<<148, 256>>>();
    hist_k<<<ETB, 256>>>(ei);
    bimg_k<<<192, 256>>>(W1l, W1r, W2l, W2r);
    scan_k<<<1, 1024>>>();
    scatter_k<<<ETB, 256>>>(ei);

    // layer 1
    gemm_tc_k<128, true><<<dim3(GT, 2), 256, SMEMB>>>(x, nullptr, nullptr,
                                                      b1hi, b1lo, xl1, xr1);
    agg_k<4, 32, 1><<<(N_NODES + 7) / 8, 256>>>(xl1, xr1, att1, b1,
                                                nullptr, hhi, hlo);
    // layer 2
    gemm_tc_k<64, false><<<dim3(GT, 1), 256, SMEMB>>>(nullptr, hhi, hlo,
                                                      b2hi, b2lo, xl2, xr2);
    agg_k<1, 64, 0><<<(N_NODES + 7) / 8, 256>>>(xl2, xr2, att2, b2,
                                                out, nullptr, nullptr);
}

// round 7
// speedup vs baseline: 1.2356x; 1.0049x over previous
#include <cuda_runtime.h>
#include <cuda_bf16.h>
#include <math.h>
#include <stdint.h>

#define N_NODES 50000
#define N_EDGES 500000
#define N_ET    (N_NODES + N_EDGES)   // 550000 edges incl. self-loops

// ---------------- static scratch (no allocations allowed) ----------------
__device__ float g_xl1[N_NODES * 128];
__device__ float g_xr1[N_NODES * 128];
__device__ __nv_bfloat16 g_hhi[N_NODES * 128];
__device__ __nv_bfloat16 g_hlo[N_NODES * 128];
__device__ float g_xl2[N_NODES * 64];
__device__ float g_xr2[N_NODES * 64];
__device__ int   g_cnt   [N_NODES];
__device__ int   g_start [N_NODES + 1];
__device__ int   g_cursor[N_NODES];
__device__ int   g_sorted[N_ET];
// bf16 weight images, plain [n][k] row-major (ldmatrix-native for B operand)
__device__ __nv_bfloat16 g_B1hi[256 * 128];
__device__ __nv_bfloat16 g_B1lo[256 * 128];
__device__ __nv_bfloat16 g_B2hi[128 * 128];
__device__ __nv_bfloat16 g_B2lo[128 * 128];

// ---------------- counting sort of edges by destination ----------------
__global__ void zero_cnt_k() {
    for (int i = blockIdx.x * blockDim.x + threadIdx.x; i < N_NODES;
         i += gridDim.x * blockDim.x)
        g_cnt[i] = 0;
}
__device__ __forceinline__ int edge_dst(const int* __restrict__ ei, int e) {
    return (e < N_EDGES) ? ei[N_EDGES + e] : (e - N_EDGES);
}
__device__ __forceinline__ int edge_src(const int* __restrict__ ei, int e) {
    return (e < N_EDGES) ? ei[e] : (e - N_EDGES);
}
__global__ void hist_k(const int* __restrict__ ei) {
    int e = blockIdx.x * blockDim.x + threadIdx.x;
    if (e < N_ET) atomicAdd(&g_cnt[edge_dst(ei, e)], 1);
}
__global__ void scan_k() {
    __shared__ int sh[1024];
    const int t = threadIdx.x;
    const int CH = (N_NODES + 1023) / 1024;  // 49
    int base = t * CH;
    int s = 0;
    for (int i = 0; i < CH; i++) {
        int idx = base + i;
        if (idx < N_NODES) s += g_cnt[idx];
    }
    sh[t] = s;
    __syncthreads();
    for (int d = 1; d < 1024; d <<= 1) {
        int v = (t >= d) ? sh[t - d] : 0;
        __syncthreads();
        sh[t] += v;
        __syncthreads();
    }
    int run = (t == 0) ? 0 : sh[t - 1];
    for (int i = 0; i < CH; i++) {
        int idx = base + i;
        if (idx < N_NODES) {
            g_start[idx]  = run;
            g_cursor[idx] = run;
            run += g_cnt[idx];
        }
    }
    if (t == 0) g_start[N_NODES] = N_ET;
}
__global__ void scatter_k(const int* __restrict__ ei) {
    int e = blockIdx.x * blockDim.x + threadIdx.x;
    if (e < N_ET) {
        int d = edge_dst(ei, e);
        int s = edge_src(ei, e);
        int pos = atomicAdd(&g_cursor[d], 1);
        g_sorted[pos] = s;
    }
}

// ---------------- weight -> bf16 hi/lo images, [n][k] row-major ----------
__global__ void bimg_k(const float* __restrict__ W1l, const float* __restrict__ W1r,
                       const float* __restrict__ W2l, const float* __restrict__ W2r) {
    int t = blockIdx.x * blockDim.x + threadIdx.x;
    if (t < 256 * 128) {                    // layer 1
        int n = t >> 7, k = t & 127;
        float v = (n < 128) ? W1l[k * 128 + n] : W1r[k * 128 + (n - 128)];
        __nv_bfloat16 h = __float2bfloat16_rn(v);
        g_B1hi[n * 128 + k] = h;
        g_B1lo[n * 128 + k] = __float2bfloat16_rn(v - __bfloat162float(h));
    } else if (t < 256 * 128 + 128 * 128) { // layer 2
        int t2 = t - 256 * 128;
        int n = t2 >> 7, k = t2 & 127;
        float v = (n < 64) ? W2l[k * 64 + n] : W2r[k * 64 + (n - 64)];
        __nv_bfloat16 h = __float2bfloat16_rn(v);
        g_B2hi[n * 128 + k] = h;
        g_B2lo[n * 128 + k] = __float2bfloat16_rn(v - __bfloat162float(h));
    }
}

// ---------------- mma.sync helpers (sm_80 baseline, works on sm_103) -----
__device__ __forceinline__ void ldsm_x4(uint32_t* r, uint32_t addr) {
    asm volatile("ldmatrix.sync.aligned.m8n8.x4.shared.b16 {%0,%1,%2,%3}, [%4];"
        : "=r"(r[0]), "=r"(r[1]), "=r"(r[2]), "=r"(r[3]) : "r"(addr));
}
__device__ __forceinline__ void mma_bf16(float* d, const uint32_t* a,
                                         uint32_t b0, uint32_t b1) {
    asm volatile("mma.sync.aligned.m16n8k16.row.col.f32.bf16.bf16.f32 "
        "{%0,%1,%2,%3}, {%4,%5,%6,%7}, {%8,%9}, {%0,%1,%2,%3};"
        : "+f"(d[0]), "+f"(d[1]), "+f"(d[2]), "+f"(d[3])
        : "r"(a[0]), "r"(a[1]), "r"(a[2]), "r"(a[3]), "r"(b0), "r"(b1));
}

// ---------------- HMMA split-bf16 dual GEMM ----------------
// D[128, 128-chunk] = Ahi@Bhi + Ahi@Blo + Alo@Bhi, fp32 accum.
// A: 128 node rows x K=128 (hi/lo). B: 128 output-cols x K=128 (hi/lo image,
// row nh*128 offset). Output cols [0,HALF) -> xl, rest -> xr.
// SMEM rows padded to 136 bf16 (272 B) for conflict-free ldmatrix.
template <int HALF, bool CONVERT>
__global__ void __launch_bounds__(256, 1)
gemm_tc_k(const float* __restrict__ xf,
          const __nv_bfloat16* __restrict__ ahi_g,
          const __nv_bfloat16* __restrict__ alo_g,
          const __nv_bfloat16* __restrict__ bhi_img,
          const __nv_bfloat16* __restrict__ blo_img,
          float* __restrict__ xl, float* __restrict__ xr) {
    extern __shared__ char smem[];
    constexpr int STRB = 272;                 // 136 bf16 per row
    constexpr int A_HI = 0;
    constexpr int A_LO = A_HI + 128 * STRB;   // 34816
    constexpr int B_HI = A_LO + 128 * STRB;
    constexpr int B_LO = B_HI + 128 * STRB;
    const int tid = threadIdx.x, wid = tid >> 5, lane = tid & 31;
    const int row0 = blockIdx.x * 128;
    const int nh   = blockIdx.y;
    uint32_t sb;
    asm("{ .reg .u64 t; cvta.to.shared.u64 t, %1; cvt.u32.u64 %0, t; }"
        : "=r"(sb) : "l"(smem));

    // ---- B tiles: row copy with padding ----
    {
        const uint4* s1 = (const uint4*)bhi_img;
        const uint4* s2 = (const uint4*)blo_img;
        for (int i = tid; i < 128 * 16; i += 256) {
            int r = i >> 4, seg = i & 15;
            *(uint4*)(smem + B_HI + r * STRB + seg * 16) = s1[(nh * 128 + r) * 16 + seg];
            *(uint4*)(smem + B_LO + r * STRB + seg * 16) = s2[(nh * 128 + r) * 16 + seg];
        }
    }
    // ---- A tiles ----
    if (CONVERT) {
        const float4* xt = (const float4*)(xf + (size_t)row0 * 128);
        for (int idx = tid; idx < 4096; idx += 256) {
            int r = idx >> 5, k4 = idx & 31, c0 = k4 * 4;
            float4 v = make_float4(0.f, 0.f, 0.f, 0.f);
            if (row0 + r < N_NODES) v = xt[idx];
            __nv_bfloat16 h0 = __float2bfloat16_rn(v.x);
            __nv_bfloat16 h1 = __float2bfloat16_rn(v.y);
            __nv_bfloat16 h2 = __float2bfloat16_rn(v.z);
            __nv_bfloat16 h3 = __float2bfloat16_rn(v.w);
            ushort hh[4] = { __bfloat16_as_ushort(h0), __bfloat16_as_ushort(h1),
                             __bfloat16_as_ushort(h2), __bfloat16_as_ushort(h3) };
            ushort ll[4] = {
                __bfloat16_as_ushort(__float2bfloat16_rn(v.x - __bfloat162float(h0))),
                __bfloat16_as_ushort(__float2bfloat16_rn(v.y - __bfloat162float(h1))),
                __bfloat16_as_ushort(__float2bfloat16_rn(v.z - __bfloat162float(h2))),
                __bfloat16_as_ushort(__float2bfloat16_rn(v.w - __bfloat162float(h3))) };
            *(uint2*)(smem + A_HI + r * STRB + c0 * 2) = *(const uint2*)hh;
            *(uint2*)(smem + A_LO + r * STRB + c0 * 2) = *(const uint2*)ll;
        }
    } else {
        const uint4* s1 = (const uint4*)ahi_g;
        const uint4* s2 = (const uint4*)alo_g;
        for (int idx = tid; idx < 2048; idx += 256) {
            int r = idx >> 4, seg = idx & 15;
            uint4 v1 = make_uint4(0u, 0u, 0u, 0u), v2 = v1;
            if (row0 + r < N_NODES) {
                v1 = s1[(size_t)(row0 + r) * 16 + seg];
                v2 = s2[(size_t)(row0 + r) * 16 + seg];
            }
            *(uint4*)(smem + A_HI + r * STRB + seg * 16) = v1;
            *(uint4*)(smem + A_LO + r * STRB + seg * 16) = v2;
        }
    }
    __syncthreads();

    // ---- mainloop: per warp, 16 rows x 128 cols ----
    const int m0 = wid * 16;
    // A ldmatrix address: lanes 0-15 rows m0..m0+15 @k, lanes 16-31 @k+8
    uint32_t aRow = m0 + (lane & 15);
    uint32_t aCol = (lane >> 4) * 16;              // bytes
    uint32_t aAddrH = sb + A_HI + aRow * STRB + aCol;
    uint32_t aAddrL = sb + A_LO + aRow * STRB + aCol;
    // B ldmatrix address: groups of 8 lanes -> (n, n k+8, n+8, n+8 k+8)
    int g = lane >> 3;
    uint32_t bRow = (lane & 7) + ((g & 2) << 2);   // +8 for g>=2
    uint32_t bCol = (g & 1) * 16;                  // bytes
    uint32_t bAddrH = sb + B_HI + bRow * STRB + bCol;
    uint32_t bAddrL = sb + B_LO + bRow * STRB + bCol;

    float acc[16][4];
    #pragma unroll
    for (int i = 0; i < 16; i++)
        #pragma unroll
        for (int j = 0; j < 4; j++) acc[i][j] = 0.f;

    #pragma unroll 1
    for (int ks = 0; ks < 8; ks++) {
        uint32_t ka = ks * 32;                     // 16 bf16 = 32 bytes
        uint32_t ah[4], al[4];
        ldsm_x4(ah, aAddrH + ka);
        ldsm_x4(al, aAddrL + ka);
        #pragma unroll
        for (int nt2 = 0; nt2 < 8; nt2++) {
            uint32_t off = nt2 * (16 * STRB) + ka;
            uint32_t bh[4], bl[4];
            ldsm_x4(bh, bAddrH + off);
            ldsm_x4(bl, bAddrL + off);
            mma_bf16(acc[nt2 * 2],     ah, bh[0], bh[1]);
            mma_bf16(acc[nt2 * 2],     ah, bl[0], bl[1]);
            mma_bf16(acc[nt2 * 2],     al, bh[0], bh[1]);
            mma_bf16(acc[nt2 * 2 + 1], ah, bh[2], bh[3]);
            mma_bf16(acc[nt2 * 2 + 1], ah, bl[2], bl[3]);
            mma_bf16(acc[nt2 * 2 + 1], al, bh[2], bh[3]);
        }
    }

    // ---- epilogue: direct float2 stores (full 32B sectors) ----
    const int rq = lane >> 2;           // 0..7
    const int cq = (lane & 3) * 2;
    const int r0g = row0 + m0 + rq;
    const int r1g = r0g + 8;
    #pragma unroll
    for (int nt = 0; nt < 16; nt++) {
        int gc = nh * 128 + nt * 8 + cq;
        float2 v0 = make_float2(acc[nt][0], acc[nt][1]);
        float2 v1 = make_float2(acc[nt][2], acc[nt][3]);
        if (gc < HALF) {
            if (r0g < N_NODES) *(float2*)&xl[(size_t)r0g * HALF + gc] = v0;
            if (r1g < N_NODES) *(float2*)&xl[(size_t)r1g * HALF + gc] = v1;
        } else {
            int g2 = gc - HALF;
            if (r0g < N_NODES) *(float2*)&xr[(size_t)r0g * HALF + g2] = v0;
            if (r1g < N_NODES) *(float2*)&xr[(size_t)r1g * HALF + g2] = v1;
        }
    }
}

// ---------------- fused GATv2 softmax + aggregation (one warp per node) --
// Single pass, no max-subtraction (scores O(5), fp32-exp safe).
// MODE 0: fp32 out + bias. MODE 1: bias + ELU, output split bf16 hi/lo.
template <int H, int C, int MODE>
__global__ void agg_k(const float* __restrict__ xl, const float* __restrict__ xr,
                      const float* __restrict__ att, const float* __restrict__ bias,
                      float* __restrict__ outf,
                      __nv_bfloat16* __restrict__ ohi, __nv_bfloat16* __restrict__ olo) {
    constexpr int HC  = H * C;
    constexpr int VEC = HC / 32;       // 4 (layer1) or 2 (layer2)
    constexpr int LPH = C / VEC;       // lanes per head
    const int lane = threadIdx.x & 31;
    const int d = blockIdx.x * (blockDim.x >> 5) + (threadIdx.x >> 5);
    if (d >= N_NODES) return;
    const int base = lane * VEC;

    float xrv[VEC], attv[VEC];
    #pragma unroll
    for (int v = 0; v < VEC; v++) {
        xrv[v]  = xr[(size_t)d * HC + base + v];
        attv[v] = att[base + v];
    }
    const int s0 = g_start[d], s1 = g_start[d + 1];

    float acc[VEC];
    #pragma unroll
    for (int v = 0; v < VEC; v++) acc[v] = 0.f;
    float den = 0.f;

    float xn[VEC];
    if (s0 < s1) {
        const float* xp = xl + (size_t)g_sorted[s0] * HC + base;
        if (VEC == 4) {
            float4 t = *(const float4*)xp;
            xn[0] = t.x; xn[1] = t.y; xn[2] = t.z; xn[3] = t.w;
        } else {
            float2 t = *(const float2*)xp;
            xn[0] = t.x; xn[1] = t.y;
        }
    }
    for (int j = s0; j < s1; j++) {
        float xv[VEC];
        #pragma unroll
        for (int v = 0; v < VEC; v++) xv[v] = xn[v];
        if (j + 1 < s1) {
            const float* xp = xl + (size_t)g_sorted[j + 1] * HC + base;
            if (VEC == 4) {
                float4 t = *(const float4*)xp;
                xn[0] = t.x; xn[1] = t.y; xn[2] = t.z; xn[3] = t.w;
            } else {
                float2 t = *(const float2*)xp;
                xn[0] = t.x; xn[1] = t.y;
            }
        }
        float s = 0.f;
        #pragma unroll
        for (int v = 0; v < VEC; v++) {
            float m = xv[v] + xrv[v];
            m = (m > 0.f) ? m : 0.2f * m;      // leaky_relu
            s = fmaf(m, attv[v], s);
        }
        #pragma unroll
        for (int w = LPH >> 1; w > 0; w >>= 1)
            s += __shfl_xor_sync(0xffffffffu, s, w);
        float p = __expf(s);
        den += p;
        #pragma unroll
        for (int v = 0; v < VEC; v++) acc[v] = fmaf(p, xv[v], acc[v]);
    }

    const float inv = 1.0f / (den + 1e-16f);
    if (MODE == 0) {
        #pragma unroll
        for (int v = 0; v < VEC; v++)
            outf[(size_t)d * HC + base + v] = acc[v] * inv + bias[base + v];
    } else {
        ushort hh[VEC], ll[VEC];
        #pragma unroll
        for (int v = 0; v < VEC; v++) {
            float r = acc[v] * inv + bias[base + v];
            r = (r > 0.f) ? r : (__expf(r) - 1.0f);   // ELU
            __nv_bfloat16 hb = __float2bfloat16_rn(r);
            hh[v] = __bfloat16_as_ushort(hb);
            ll[v] = __bfloat16_as_ushort(__float2bfloat16_rn(r - __bfloat162float(hb)));
        }
        size_t o = ((size_t)d * HC + base) >> 2;      // VEC==4: uint2 granules
        ((uint2*)ohi)[o] = *(const uint2*)hh;
        ((uint2*)olo)[o] = *(const uint2*)ll;
    }
}

// ---------------- launch ----------------
extern "C" void kernel_launch(void* const* d_in, const int* in_sizes, int n_in,
                              void* d_out, int out_size) {
    const float* x    = (const float*)d_in[0];
    const int*   ei   = (const int*)  d_in[1];
    const float* W1l  = (const float*)d_in[2];
    const float* W1r  = (const float*)d_in[3];
    const float* att1 = (const float*)d_in[4];
    const float* b1   = (const float*)d_in[5];
    const float* W2l  = (const float*)d_in[6];
    const float* W2r  = (const float*)d_in[7];
    const float* att2 = (const float*)d_in[8];
    const float* b2   = (const float*)d_in[9];
    float* out = (float*)d_out;

    float *xl1, *xr1, *xl2, *xr2;
    __nv_bfloat16 *hhi, *hlo, *b1hi, *b1lo, *b2hi, *b2lo;
    cudaGetSymbolAddress((void**)&xl1, g_xl1);
    cudaGetSymbolAddress((void**)&xr1, g_xr1);
    cudaGetSymbolAddress((void**)&hhi, g_hhi);
    cudaGetSymbolAddress((void**)&hlo, g_hlo);
    cudaGetSymbolAddress((void**)&xl2, g_xl2);
    cudaGetSymbolAddress((void**)&xr2, g_xr2);
    cudaGetSymbolAddress((void**)&b1hi, g_B1hi);
    cudaGetSymbolAddress((void**)&b1lo, g_B1lo);
    cudaGetSymbolAddress((void**)&b2hi, g_B2hi);
    cudaGetSymbolAddress((void**)&b2lo, g_B2lo);

    constexpr int SMEMB = 4 * 128 * 272;   // 139264
    cudaFuncSetAttribute(gemm_tc_k<128, true>,
                         cudaFuncAttributeMaxDynamicSharedMemorySize, SMEMB);
    cudaFuncSetAttribute(gemm_tc_k<64, false>,
                         cudaFuncAttributeMaxDynamicSharedMemorySize, SMEMB);

    const int ETB = (N_ET + 255) / 256;
    const int GT  = (N_NODES + 127) / 128;   // 391 gemm tiles

    // edge CSR (sorted by dst)
    zero_cnt_k<<<148, 256>>>();
    hist_k<<<ETB, 256>>>(ei);
    bimg_k<<<192, 256>>>(W1l, W1r, W2l, W2r);
    scan_k<<<1, 1024>>>();
    scatter_k<<<ETB, 256>>>(ei);

    // layer 1
    gemm_tc_k<128, true><<<dim3(GT, 2), 256, SMEMB>>>(x, nullptr, nullptr,
                                                      b1hi, b1lo, xl1, xr1);
    agg_k<4, 32, 1><<<(N_NODES + 7) / 8, 256>>>(xl1, xr1, att1, b1,
                                                nullptr, hhi, hlo);
    // layer 2
    gemm_tc_k<64, false><<<dim3(GT, 1), 256, SMEMB>>>(nullptr, hhi, hlo,
                                                      b2hi, b2lo, xl2, xr2);
    agg_k<1, 64, 0><<<(N_NODES + 7) / 8, 256>>>(xl2, xr2, att2, b2,
                                                out, nullptr, nullptr);
}

// round 8
// speedup vs baseline: 1.6500x; 1.3354x over previous
#include <cuda_runtime.h>
#include <cuda_bf16.h>
#include <math.h>
#include <stdint.h>

#define N_NODES 50000
#define N_EDGES 500000
#define N_ET    (N_NODES + N_EDGES)   // 550000 edges incl. self-loops
#define NB_SCAN ((N_NODES + 255) / 256)   // 196 scan blocks

// ---------------- static scratch (no allocations allowed) ----------------
__device__ float g_xl1[N_NODES * 128];
__device__ float g_xr1[N_NODES * 128];
__device__ __nv_bfloat16 g_hhi[N_NODES * 128];
__device__ __nv_bfloat16 g_hlo[N_NODES * 128];
__device__ float g_xl2[N_NODES * 64];
__device__ float g_xr2[N_NODES * 64];
__device__ int   g_cnt   [N_NODES];
__device__ int   g_start [N_NODES + 1];
__device__ int   g_cursor[N_NODES];
__device__ int   g_sorted[N_ET];
__device__ int   g_bsum  [256];
// bf16 weight images, plain [n][k] row-major (ldmatrix-native for B operand)
__device__ __nv_bfloat16 g_B1hi[256 * 128];
__device__ __nv_bfloat16 g_B1lo[256 * 128];
__device__ __nv_bfloat16 g_B2hi[128 * 128];
__device__ __nv_bfloat16 g_B2lo[128 * 128];

// ---------------- counting sort of edges by destination ----------------
__global__ void zero_cnt_k() {
    for (int i = blockIdx.x * blockDim.x + threadIdx.x; i < N_NODES;
         i += gridDim.x * blockDim.x)
        g_cnt[i] = 0;
}
__device__ __forceinline__ int edge_dst(const int* __restrict__ ei, int e) {
    return (e < N_EDGES) ? ei[N_EDGES + e] : (e - N_EDGES);
}
__device__ __forceinline__ int edge_src(const int* __restrict__ ei, int e) {
    return (e < N_EDGES) ? ei[e] : (e - N_EDGES);
}
__global__ void hist_k(const int* __restrict__ ei) {
    int e = blockIdx.x * blockDim.x + threadIdx.x;
    if (e < N_ET) atomicAdd(&g_cnt[edge_dst(ei, e)], 1);
}

// ---------------- three-phase multi-block exclusive scan ----------------
__global__ void scan1_k() {               // per-block reduction
    __shared__ int sh[256];
    int i = blockIdx.x * 256 + threadIdx.x;
    int v = (i < N_NODES) ? g_cnt[i] : 0;
    sh[threadIdx.x] = v;
    __syncthreads();
    #pragma unroll
    for (int d = 128; d > 0; d >>= 1) {
        if (threadIdx.x < d) sh[threadIdx.x] += sh[threadIdx.x + d];
        __syncthreads();
    }
    if (threadIdx.x == 0) g_bsum[blockIdx.x] = sh[0];
}
__global__ void scan2_k() {               // scan the 196 block sums
    __shared__ int sh[256];
    int t = threadIdx.x;
    int v = (t < NB_SCAN) ? g_bsum[t] : 0;
    sh[t] = v;
    __syncthreads();
    #pragma unroll
    for (int d = 1; d < 256; d <<= 1) {
        int u = (t >= d) ? sh[t - d] : 0;
        __syncthreads();
        sh[t] += u;
        __syncthreads();
    }
    if (t < NB_SCAN) g_bsum[t] = sh[t] - v;   // exclusive
    if (t == 0) g_start[N_NODES] = N_ET;
}
__global__ void scan3_k() {               // per-block exclusive scan + offset
    __shared__ int sh[256];
    int t = threadIdx.x;
    int i = blockIdx.x * 256 + t;
    int v = (i < N_NODES) ? g_cnt[i] : 0;
    sh[t] = v;
    __syncthreads();
    #pragma unroll
    for (int d = 1; d < 256; d <<= 1) {
        int u = (t >= d) ? sh[t - d] : 0;
        __syncthreads();
        sh[t] += u;
        __syncthreads();
    }
    int ex = sh[t] - v + g_bsum[blockIdx.x];
    if (i < N_NODES) { g_start[i] = ex; g_cursor[i] = ex; }
}

__global__ void scatter_k(const int* __restrict__ ei) {
    int e = blockIdx.x * blockDim.x + threadIdx.x;
    if (e < N_ET) {
        int d = edge_dst(ei, e);
        int s = edge_src(ei, e);
        int pos = atomicAdd(&g_cursor[d], 1);
        g_sorted[pos] = s;
    }
}

// ---------------- weight -> bf16 hi/lo images, [n][k] row-major ----------
__global__ void bimg_k(const float* __restrict__ W1l, const float* __restrict__ W1r,
                       const float* __restrict__ W2l, const float* __restrict__ W2r) {
    int t = blockIdx.x * blockDim.x + threadIdx.x;
    if (t < 256 * 128) {                    // layer 1
        int n = t >> 7, k = t & 127;
        float v = (n < 128) ? W1l[k * 128 + n] : W1r[k * 128 + (n - 128)];
        __nv_bfloat16 h = __float2bfloat16_rn(v);
        g_B1hi[n * 128 + k] = h;
        g_B1lo[n * 128 + k] = __float2bfloat16_rn(v - __bfloat162float(h));
    } else if (t < 256 * 128 + 128 * 128) { // layer 2
        int t2 = t - 256 * 128;
        int n = t2 >> 7, k = t2 & 127;
        float v = (n < 64) ? W2l[k * 64 + n] : W2r[k * 64 + (n - 64)];
        __nv_bfloat16 h = __float2bfloat16_rn(v);
        g_B2hi[n * 128 + k] = h;
        g_B2lo[n * 128 + k] = __float2bfloat16_rn(v - __bfloat162float(h));
    }
}

// ---------------- mma.sync helpers (sm_80 baseline, works on sm_103) -----
__device__ __forceinline__ void ldsm_x4(uint32_t* r, uint32_t addr) {
    asm volatile("ldmatrix.sync.aligned.m8n8.x4.shared.b16 {%0,%1,%2,%3}, [%4];"
        : "=r"(r[0]), "=r"(r[1]), "=r"(r[2]), "=r"(r[3]) : "r"(addr));
}
__device__ __forceinline__ void mma_bf16(float* d, const uint32_t* a,
                                         uint32_t b0, uint32_t b1) {
    asm volatile("mma.sync.aligned.m16n8k16.row.col.f32.bf16.bf16.f32 "
        "{%0,%1,%2,%3}, {%4,%5,%6,%7}, {%8,%9}, {%0,%1,%2,%3};"
        : "+f"(d[0]), "+f"(d[1]), "+f"(d[2]), "+f"(d[3])
        : "r"(a[0]), "r"(a[1]), "r"(a[2]), "r"(a[3]), "r"(b0), "r"(b1));
}

// ---------------- HMMA split-bf16 dual GEMM ----------------
// D[128, 128-chunk] = Ahi@Bhi + Ahi@Blo + Alo@Bhi, fp32 accum.
// A: 128 node rows x K=128 (hi/lo). B: 128 output-cols x K=128 (hi/lo image,
// row nh*128 offset). Output cols [0,HALF) -> xl, rest -> xr.
// SMEM rows padded to 136 bf16 (272 B) for conflict-free ldmatrix.
template <int HALF, bool CONVERT>
__global__ void __launch_bounds__(256, 1)
gemm_tc_k(const float* __restrict__ xf,
          const __nv_bfloat16* __restrict__ ahi_g,
          const __nv_bfloat16* __restrict__ alo_g,
          const __nv_bfloat16* __restrict__ bhi_img,
          const __nv_bfloat16* __restrict__ blo_img,
          float* __restrict__ xl, float* __restrict__ xr) {
    extern __shared__ char smem[];
    constexpr int STRB = 272;                 // 136 bf16 per row
    constexpr int A_HI = 0;
    constexpr int A_LO = A_HI + 128 * STRB;   // 34816
    constexpr int B_HI = A_LO + 128 * STRB;
    constexpr int B_LO = B_HI + 128 * STRB;
    const int tid = threadIdx.x, wid = tid >> 5, lane = tid & 31;
    const int row0 = blockIdx.x * 128;
    const int nh   = blockIdx.y;
    uint32_t sb;
    asm("{ .reg .u64 t; cvta.to.shared.u64 t, %1; cvt.u32.u64 %0, t; }"
        : "=r"(sb) : "l"(smem));

    // ---- B tiles: row copy with padding ----
    {
        const uint4* s1 = (const uint4*)bhi_img;
        const uint4* s2 = (const uint4*)blo_img;
        for (int i = tid; i < 128 * 16; i += 256) {
            int r = i >> 4, seg = i & 15;
            *(uint4*)(smem + B_HI + r * STRB + seg * 16) = s1[(nh * 128 + r) * 16 + seg];
            *(uint4*)(smem + B_LO + r * STRB + seg * 16) = s2[(nh * 128 + r) * 16 + seg];
        }
    }
    // ---- A tiles ----
    if (CONVERT) {
        const float4* xt = (const float4*)(xf + (size_t)row0 * 128);
        for (int idx = tid; idx < 4096; idx += 256) {
            int r = idx >> 5, k4 = idx & 31, c0 = k4 * 4;
            float4 v = make_float4(0.f, 0.f, 0.f, 0.f);
            if (row0 + r < N_NODES) v = xt[idx];
            __nv_bfloat16 h0 = __float2bfloat16_rn(v.x);
            __nv_bfloat16 h1 = __float2bfloat16_rn(v.y);
            __nv_bfloat16 h2 = __float2bfloat16_rn(v.z);
            __nv_bfloat16 h3 = __float2bfloat16_rn(v.w);
            ushort hh[4] = { __bfloat16_as_ushort(h0), __bfloat16_as_ushort(h1),
                             __bfloat16_as_ushort(h2), __bfloat16_as_ushort(h3) };
            ushort ll[4] = {
                __bfloat16_as_ushort(__float2bfloat16_rn(v.x - __bfloat162float(h0))),
                __bfloat16_as_ushort(__float2bfloat16_rn(v.y - __bfloat162float(h1))),
                __bfloat16_as_ushort(__float2bfloat16_rn(v.z - __bfloat162float(h2))),
                __bfloat16_as_ushort(__float2bfloat16_rn(v.w - __bfloat162float(h3))) };
            *(uint2*)(smem + A_HI + r * STRB + c0 * 2) = *(const uint2*)hh;
            *(uint2*)(smem + A_LO + r * STRB + c0 * 2) = *(const uint2*)ll;
        }
    } else {
        const uint4* s1 = (const uint4*)ahi_g;
        const uint4* s2 = (const uint4*)alo_g;
        for (int idx = tid; idx < 2048; idx += 256) {
            int r = idx >> 4, seg = idx & 15;
            uint4 v1 = make_uint4(0u, 0u, 0u, 0u), v2 = v1;
            if (row0 + r < N_NODES) {
                v1 = s1[(size_t)(row0 + r) * 16 + seg];
                v2 = s2[(size_t)(row0 + r) * 16 + seg];
            }
            *(uint4*)(smem + A_HI + r * STRB + seg * 16) = v1;
            *(uint4*)(smem + A_LO + r * STRB + seg * 16) = v2;
        }
    }
    __syncthreads();

    // ---- mainloop: per warp, 16 rows x 128 cols ----
    const int m0 = wid * 16;
    uint32_t aRow = m0 + (lane & 15);
    uint32_t aCol = (lane >> 4) * 16;              // bytes
    uint32_t aAddrH = sb + A_HI + aRow * STRB + aCol;
    uint32_t aAddrL = sb + A_LO + aRow * STRB + aCol;
    int g = lane >> 3;
    uint32_t bRow = (lane & 7) + ((g & 2) << 2);   // +8 for g>=2
    uint32_t bCol = (g & 1) * 16;                  // bytes
    uint32_t bAddrH = sb + B_HI + bRow * STRB + bCol;
    uint32_t bAddrL = sb + B_LO + bRow * STRB + bCol;

    float acc[16][4];
    #pragma unroll
    for (int i = 0; i < 16; i++)
        #pragma unroll
        for (int j = 0; j < 4; j++) acc[i][j] = 0.f;

    #pragma unroll 1
    for (int ks = 0; ks < 8; ks++) {
        uint32_t ka = ks * 32;                     // 16 bf16 = 32 bytes
        uint32_t ah[4], al[4];
        ldsm_x4(ah, aAddrH + ka);
        ldsm_x4(al, aAddrL + ka);
        #pragma unroll
        for (int nt2 = 0; nt2 < 8; nt2++) {
            uint32_t off = nt2 * (16 * STRB) + ka;
            uint32_t bh[4], bl[4];
            ldsm_x4(bh, bAddrH + off);
            ldsm_x4(bl, bAddrL + off);
            mma_bf16(acc[nt2 * 2],     ah, bh[0], bh[1]);
            mma_bf16(acc[nt2 * 2],     ah, bl[0], bl[1]);
            mma_bf16(acc[nt2 * 2],     al, bh[0], bh[1]);
            mma_bf16(acc[nt2 * 2 + 1], ah, bh[2], bh[3]);
            mma_bf16(acc[nt2 * 2 + 1], ah, bl[2], bl[3]);
            mma_bf16(acc[nt2 * 2 + 1], al, bh[2], bh[3]);
        }
    }

    // ---- epilogue: direct float2 stores (full 32B sectors) ----
    const int rq = lane >> 2;           // 0..7
    const int cq = (lane & 3) * 2;
    const int r0g = row0 + m0 + rq;
    const int r1g = r0g + 8;
    #pragma unroll
    for (int nt = 0; nt < 16; nt++) {
        int gc = nh * 128 + nt * 8 + cq;
        float2 v0 = make_float2(acc[nt][0], acc[nt][1]);
        float2 v1 = make_float2(acc[nt][2], acc[nt][3]);
        if (gc < HALF) {
            if (r0g < N_NODES) *(float2*)&xl[(size_t)r0g * HALF + gc] = v0;
            if (r1g < N_NODES) *(float2*)&xl[(size_t)r1g * HALF + gc] = v1;
        } else {
            int g2 = gc - HALF;
            if (r0g < N_NODES) *(float2*)&xr[(size_t)r0g * HALF + g2] = v0;
            if (r1g < N_NODES) *(float2*)&xr[(size_t)r1g * HALF + g2] = v1;
        }
    }
}

// ---------------- fused GATv2 softmax + aggregation (one warp per node) --
// Single pass, no max-subtraction (scores O(5), fp32-exp safe).
// MODE 0: fp32 out + bias. MODE 1: bias + ELU, output split bf16 hi/lo.
template <int H, int C, int MODE>
__global__ void agg_k(const float* __restrict__ xl, const float* __restrict__ xr,
                      const float* __restrict__ att, const float* __restrict__ bias,
                      float* __restrict__ outf,
                      __nv_bfloat16* __restrict__ ohi, __nv_bfloat16* __restrict__ olo) {
    constexpr int HC  = H * C;
    constexpr int VEC = HC / 32;       // 4 (layer1) or 2 (layer2)
    constexpr int LPH = C / VEC;       // lanes per head
    const int lane = threadIdx.x & 31;
    const int d = blockIdx.x * (blockDim.x >> 5) + (threadIdx.x >> 5);
    if (d >= N_NODES) return;
    const int base = lane * VEC;

    float xrv[VEC], attv[VEC];
    #pragma unroll
    for (int v = 0; v < VEC; v++) {
        xrv[v]  = xr[(size_t)d * HC + base + v];
        attv[v] = att[base + v];
    }
    const int s0 = g_start[d], s1 = g_start[d + 1];

    float acc[VEC];
    #pragma unroll
    for (int v = 0; v < VEC; v++) acc[v] = 0.f;
    float den = 0.f;

    float xn[VEC];
    if (s0 < s1) {
        const float* xp = xl + (size_t)g_sorted[s0] * HC + base;
        if (VEC == 4) {
            float4 t = *(const float4*)xp;
            xn[0] = t.x; xn[1] = t.y; xn[2] = t.z; xn[3] = t.w;
        } else {
            float2 t = *(const float2*)xp;
            xn[0] = t.x; xn[1] = t.y;
        }
    }
    for (int j = s0; j < s1; j++) {
        float xv[VEC];
        #pragma unroll
        for (int v = 0; v < VEC; v++) xv[v] = xn[v];
        if (j + 1 < s1) {
            const float* xp = xl + (size_t)g_sorted[j + 1] * HC + base;
            if (VEC == 4) {
                float4 t = *(const float4*)xp;
                xn[0] = t.x; xn[1] = t.y; xn[2] = t.z; xn[3] = t.w;
            } else {
                float2 t = *(const float2*)xp;
                xn[0] = t.x; xn[1] = t.y;
            }
        }
        float s = 0.f;
        #pragma unroll
        for (int v = 0; v < VEC; v++) {
            float m = xv[v] + xrv[v];
            m = (m > 0.f) ? m : 0.2f * m;      // leaky_relu
            s = fmaf(m, attv[v], s);
        }
        #pragma unroll
        for (int w = LPH >> 1; w > 0; w >>= 1)
            s += __shfl_xor_sync(0xffffffffu, s, w);
        float p = __expf(s);
        den += p;
        #pragma unroll
        for (int v = 0; v < VEC; v++) acc[v] = fmaf(p, xv[v], acc[v]);
    }

    const float inv = 1.0f / (den + 1e-16f);
    if (MODE == 0) {
        #pragma unroll
        for (int v = 0; v < VEC; v++)
            outf[(size_t)d * HC + base + v] = acc[v] * inv + bias[base + v];
    } else {
        ushort hh[VEC], ll[VEC];
        #pragma unroll
        for (int v = 0; v < VEC; v++) {
            float r = acc[v] * inv + bias[base + v];
            r = (r > 0.f) ? r : (__expf(r) - 1.0f);   // ELU
            __nv_bfloat16 hb = __float2bfloat16_rn(r);
            hh[v] = __bfloat16_as_ushort(hb);
            ll[v] = __bfloat16_as_ushort(__float2bfloat16_rn(r - __bfloat162float(hb)));
        }
        size_t o = ((size_t)d * HC + base) >> 2;      // VEC==4: uint2 granules
        ((uint2*)ohi)[o] = *(const uint2*)hh;
        ((uint2*)olo)[o] = *(const uint2*)ll;
    }
}

// ---------------- launch ----------------
extern "C" void kernel_launch(void* const* d_in, const int* in_sizes, int n_in,
                              void* d_out, int out_size) {
    const float* x    = (const float*)d_in[0];
    const int*   ei   = (const int*)  d_in[1];
    const float* W1l  = (const float*)d_in[2];
    const float* W1r  = (const float*)d_in[3];
    const float* att1 = (const float*)d_in[4];
    const float* b1   = (const float*)d_in[5];
    const float* W2l  = (const float*)d_in[6];
    const float* W2r  = (const float*)d_in[7];
    const float* att2 = (const float*)d_in[8];
    const float* b2   = (const float*)d_in[9];
    float* out = (float*)d_out;

    float *xl1, *xr1, *xl2, *xr2;
    __nv_bfloat16 *hhi, *hlo, *b1hi, *b1lo, *b2hi, *b2lo;
    cudaGetSymbolAddress((void**)&xl1, g_xl1);
    cudaGetSymbolAddress((void**)&xr1, g_xr1);
    cudaGetSymbolAddress((void**)&hhi, g_hhi);
    cudaGetSymbolAddress((void**)&hlo, g_hlo);
    cudaGetSymbolAddress((void**)&xl2, g_xl2);
    cudaGetSymbolAddress((void**)&xr2, g_xr2);
    cudaGetSymbolAddress((void**)&b1hi, g_B1hi);
    cudaGetSymbolAddress((void**)&b1lo, g_B1lo);
    cudaGetSymbolAddress((void**)&b2hi, g_B2hi);
    cudaGetSymbolAddress((void**)&b2lo, g_B2lo);

    constexpr int SMEMB = 4 * 128 * 272;   // 139264
    cudaFuncSetAttribute(gemm_tc_k<128, true>,
                         cudaFuncAttributeMaxDynamicSharedMemorySize, SMEMB);
    cudaFuncSetAttribute(gemm_tc_k<64, false>,
                         cudaFuncAttributeMaxDynamicSharedMemorySize, SMEMB);

    const int ETB = (N_ET + 255) / 256;
    const int GT  = (N_NODES + 127) / 128;   // 391 gemm tiles

    // edge CSR (sorted by dst) — parallel 3-phase scan
    zero_cnt_k<<<148, 256>>>();
    hist_k<<<ETB, 256>>>(ei);
    bimg_k<<<192, 256>>>(W1l, W1r, W2l, W2r);
    scan1_k<<<NB_SCAN, 256>>>();
    scan2_k<<<1, 256>>>();
    scan3_k<<<NB_SCAN, 256>>>();
    scatter_k<<<ETB, 256>>>(ei);

    // layer 1
    gemm_tc_k<128, true><<<dim3(GT, 2), 256, SMEMB>>>(x, nullptr, nullptr,
                                                      b1hi, b1lo, xl1, xr1);
    agg_k<4, 32, 1><<<(N_NODES + 7) / 8, 256>>>(xl1, xr1, att1, b1,
                                                nullptr, hhi, hlo);
    // layer 2
    gemm_tc_k<64, false><<<dim3(GT, 1), 256, SMEMB>>>(nullptr, hhi, hlo,
                                                      b2hi, b2lo, xl2, xr2);
    agg_k<1, 64, 0><<<(N_NODES + 7) / 8, 256>>>(xl2, xr2, att2, b2,
                                                out, nullptr, nullptr);
}